// round 9
// baseline (speedup 1.0000x reference)
#include <cuda_runtime.h>
#include <cuda_bf16.h>

#define GSZ 8
#define DIMN 160
#define N3 (DIMN*DIMN*DIMN)
#define NLINES (4 * DIMN * DIMN * 3)          // b * d * h * component

// Precomputed per-(b,d,h,c) x-node lerp pairs: (g[i], g[min(i+1,7)])
__device__ float2 gnodes[NLINES * GSZ];       // 19.66 MB scratch

__global__ void __launch_bounds__(256) flow_nodes_kernel(
    const float* __restrict__ flow)           // [B,3,8,8,8]
{
    const int t = blockIdx.x * blockDim.x + threadIdx.x;
    if (t >= NLINES) return;
    const int c  = t % 3;
    int r        = t / 3;
    const int h  = r % DIMN;
    r            = r / DIMN;
    const int d  = r % DIMN;
    const int b  = r / DIMN;

    const float s = 7.0f / 159.0f;
    const float cz = d * s, cy = h * s;
    const int   iz0 = (int)cz, iy0 = (int)cy;
    const float fz = cz - iz0, fy = cy - iy0;
    const int   iz1 = min(iz0 + 1, GSZ - 1);
    const int   iy1 = min(iy0 + 1, GSZ - 1);

    // flow rows are 32B contiguous & aligned -> float4 pairs
    const float4* fb = (const float4*)(flow + (((size_t)b * 3 + c) << 9));
    const float4 r00a = fb[(iz0 * GSZ + iy0) * 2], r00b = fb[(iz0 * GSZ + iy0) * 2 + 1];
    const float4 r01a = fb[(iz0 * GSZ + iy1) * 2], r01b = fb[(iz0 * GSZ + iy1) * 2 + 1];
    const float4 r10a = fb[(iz1 * GSZ + iy0) * 2], r10b = fb[(iz1 * GSZ + iy0) * 2 + 1];
    const float4 r11a = fb[(iz1 * GSZ + iy1) * 2], r11b = fb[(iz1 * GSZ + iy1) * 2 + 1];

    float g[8];
    {
        const float* a0 = (const float*)&r00a;  // nodes 0-3, y0,z0
        const float* a1 = (const float*)&r00b;  // nodes 4-7
        const float* b0 = (const float*)&r01a;
        const float* b1 = (const float*)&r01b;
        const float* c0 = (const float*)&r10a;
        const float* c1 = (const float*)&r10b;
        const float* d0 = (const float*)&r11a;
        const float* d1 = (const float*)&r11b;
        #pragma unroll
        for (int i = 0; i < 4; i++) {
            float v0 = a0[i] + fy * (b0[i] - a0[i]);
            float v1 = c0[i] + fy * (d0[i] - c0[i]);
            g[i] = v0 + fz * (v1 - v0);
            float w0 = a1[i] + fy * (b1[i] - a1[i]);
            float w1 = c1[i] + fy * (d1[i] - c1[i]);
            g[4 + i] = w0 + fz * (w1 - w0);
        }
    }

    float2* outp = gnodes + (size_t)t * GSZ;
    #pragma unroll
    for (int i = 0; i < GSZ; i++) {
        float2 p;
        p.x = g[i];
        p.y = g[min(i + 1, GSZ - 1)];
        outp[i] = p;
    }
}

__device__ __forceinline__ float reflect1(float c) {
    // mirror, period 2*(n-1)=318; single fold valid since |delta| <= ~16
    c = fabsf(c);
    return (c > 159.0f) ? (318.0f - c) : c;
}

__global__ void __launch_bounds__(256) elastic_kernel(
    const float* __restrict__ x,       // [B,2,160,160,160]
    float* __restrict__ out)           // [B,2,160,160,160]
{
    // block: 32 w x 8 h ; grid: (5 w-tiles, 20 h-tiles * 160 d, 4 b)
    const int b  = blockIdx.z;
    const int d  = blockIdx.y / 20;
    const int ht = blockIdx.y % 20;
    const int tx = threadIdx.x;
    const int h  = ht * 8 + threadIdx.y;
    const int w  = blockIdx.x * 32 + tx;

    // ---- coarse flow: one LDG.64 per component from precomputed node pairs ----
    const float s = 7.0f / 159.0f;
    const float cx  = w * s;
    const int   ix0 = (int)cx;
    const float fx  = cx - ix0;

    const float2* gp = gnodes + ((((size_t)b * DIMN + d) * DIMN + h) * 3) * GSZ;
    const float2 p0 = __ldg(gp + ix0);
    const float2 p1 = __ldg(gp + GSZ + ix0);
    const float2 p2 = __ldg(gp + 2 * GSZ + ix0);
    const float upx = p0.x + fx * (p0.y - p0.x);
    const float upy = p1.x + fx * (p1.y - p1.x);
    const float upz = p2.x + fx * (p2.y - p2.x);

    // ---- warp coordinate: voxel + up*(n-1)/2, mirror-reflect (single fold) ----
    const float px = reflect1((float)w + upx * 79.5f);
    const float py = reflect1((float)h + upy * 79.5f);
    const float pz = reflect1((float)d + upz * 79.5f);

    // px,py,pz in [0,159] -> floor tap needs no clamp
    const int jx0 = (int)px;
    const int jy0 = (int)py;
    const int jz0 = (int)pz;
    const float ax = px - (float)jx0;
    const float ay = py - (float)jy0;
    const float az = pz - (float)jz0;

    const int dx = (jx0 < DIMN - 1) ? 1         : 0;
    const int dy = (jy0 < DIMN - 1) ? DIMN      : 0;
    const int dz = (jz0 < DIMN - 1) ? DIMN*DIMN : 0;

    const float bx0 = 1.0f - ax, by0 = 1.0f - ay, bz0 = 1.0f - az;
    const float w00 = bz0 * by0, w01 = bz0 * ay;
    const float w10 = az * by0,  w11 = az * ay;
    float tw[8];
    tw[0] = w00 * bx0;  tw[1] = w00 * ax;
    tw[2] = w01 * bx0;  tw[3] = w01 * ax;
    tw[4] = w10 * bx0;  tw[5] = w10 * ax;
    tw[6] = w11 * bx0;  tw[7] = w11 * ax;

    const int base = (jz0 * DIMN + jy0) * DIMN + jx0;
    int off[8];
    off[0] = base;          off[1] = base + dx;
    off[2] = off[0] + dy;   off[3] = off[2] + dx;
    off[4] = off[0] + dz;   off[5] = off[4] + dx;
    off[6] = off[4] + dy;   off[7] = off[6] + dx;

    const float* __restrict__ x0 = x + (size_t)b * 2 * N3;   // ch0; +N3 = ch1

    float t0[8], t1[8];
    #pragma unroll
    for (int k = 0; k < 8; k++) {
        const float* p = x0 + off[k];
        t0[k] = __ldg(p);
        t1[k] = __ldg(p + N3);
    }

    float v0 = 0.f, v1 = 0.f;
    #pragma unroll
    for (int k = 0; k < 8; k++) {
        v0 = fmaf(tw[k], t0[k], v0);
        v1 = fmaf(tw[k], t1[k], v1);
    }

    const int spatial = (d * DIMN + h) * DIMN + w;
    float* __restrict__ o0 = out + (size_t)b * 2 * N3;
    o0[spatial]      = v0;
    o0[N3 + spatial] = v1;
}

extern "C" void kernel_launch(void* const* d_in, const int* in_sizes, int n_in,
                              void* d_out, int out_size) {
    const float* x    = (const float*)d_in[0];
    const float* flow = (const float*)d_in[1];
    float* out        = (float*)d_out;

    flow_nodes_kernel<<<(NLINES + 255) / 256, 256>>>(flow);

    dim3 block(32, 8);                 // 256 threads: 32 w x 8 h
    dim3 grid(5, 20 * DIMN, 4);        // (w-tiles, h-tiles*d, b)
    elastic_kernel<<<grid, block>>>(x, out);
}

// round 10
// speedup vs baseline: 1.0389x; 1.0389x over previous
#include <cuda_runtime.h>
#include <cuda_bf16.h>

#define GSZ 8
#define DIMN 160
#define N3 (DIMN*DIMN*DIMN)
#define NLINES (4 * DIMN * DIMN * 3)          // b * d * h * component

// Precomputed per-(b,d,h,c) x-node lerp pairs: (g[i], g[min(i+1,7)])
__device__ float2 gnodes[NLINES * GSZ];       // 19.66 MB scratch

// One thread per (b, d, h, c, half): computes 4 node-pairs (32 B).
// block = 192 threads = 32 h-lines x (3 comp x 2 half); grid = (5 h-tiles, 160 d, 4 b)
__global__ void __launch_bounds__(192) flow_nodes_kernel(
    const float* __restrict__ flow)           // [B,3,8,8,8]
{
    const int tid = threadIdx.x;
    const int hl   = tid / 6;                 // 0..31
    const int r    = tid - hl * 6;
    const int c    = r >> 1;                  // component 0..2
    const int half = r & 1;                   // node group: 0 -> nodes 0..3, 1 -> 4..7
    const int h    = blockIdx.x * 32 + hl;
    const int d    = blockIdx.y;
    const int b    = blockIdx.z;

    const float s = 7.0f / 159.0f;
    const float cz = d * s, cy = h * s;
    const int   iz0 = (int)cz, iy0 = (int)cy;
    const float fz = cz - iz0, fy = cy - iy0;
    const int   iz1 = min(iz0 + 1, GSZ - 1);
    const int   iy1 = min(iy0 + 1, GSZ - 1);

    const float* fb = flow + (((size_t)b * 3 + c) << 9);   // *512
    const int base = half * 4;                             // first node of this half
    const int r00 = (iz0 * GSZ + iy0) * GSZ;
    const int r01 = (iz0 * GSZ + iy1) * GSZ;
    const int r10 = (iz1 * GSZ + iy0) * GSZ;
    const int r11 = (iz1 * GSZ + iy1) * GSZ;

    // rows are 32B-aligned; +base (0 or 16B) keeps 16B alignment for float4
    const float4 a = *(const float4*)(fb + r00 + base);
    const float4 bq = *(const float4*)(fb + r01 + base);
    const float4 cq = *(const float4*)(fb + r10 + base);
    const float4 dq = *(const float4*)(fb + r11 + base);
    const int nx = min(base + 4, GSZ - 1);                 // clamped next node
    const float ea = fb[r00 + nx];
    const float eb = fb[r01 + nx];
    const float ec = fb[r10 + nx];
    const float ed = fb[r11 + nx];

    float g[5];
    {
        const float* pa = (const float*)&a;
        const float* pb = (const float*)&bq;
        const float* pc = (const float*)&cq;
        const float* pd = (const float*)&dq;
        #pragma unroll
        for (int i = 0; i < 4; i++) {
            const float v0 = pa[i] + fy * (pb[i] - pa[i]);
            const float v1 = pc[i] + fy * (pd[i] - pc[i]);
            g[i] = v0 + fz * (v1 - v0);
        }
        const float v0 = ea + fy * (eb - ea);
        const float v1 = ec + fy * (ed - ec);
        g[4] = v0 + fz * (v1 - v0);
    }

    // 4 pairs (g[i], g[i+1]) -> 2 x STG.128, 16B-aligned
    float4 o0, o1;
    o0.x = g[0]; o0.y = g[1]; o0.z = g[1]; o0.w = g[2];
    o1.x = g[2]; o1.y = g[3]; o1.z = g[3]; o1.w = g[4];
    float4* outp = (float4*)(gnodes
        + ((((size_t)b * DIMN + d) * DIMN + h) * 3 + c) * GSZ + base);
    outp[0] = o0;
    outp[1] = o1;
}

__device__ __forceinline__ float reflect1(float c) {
    // mirror, period 2*(n-1)=318; single fold valid since |delta| <= ~16
    c = fabsf(c);
    return (c > 159.0f) ? (318.0f - c) : c;
}

__global__ void __launch_bounds__(256) elastic_kernel(
    const float* __restrict__ x,       // [B,2,160,160,160]
    float* __restrict__ out)           // [B,2,160,160,160]
{
    // block: 32 w x 8 h ; grid: (5 w-tiles, 20 h-tiles * 160 d, 4 b)
    const int b  = blockIdx.z;
    const int d  = blockIdx.y / 20;
    const int ht = blockIdx.y % 20;
    const int tx = threadIdx.x;
    const int h  = ht * 8 + threadIdx.y;
    const int w  = blockIdx.x * 32 + tx;

    // ---- coarse flow: one LDG.64 per component from precomputed node pairs ----
    const float s = 7.0f / 159.0f;
    const float cx  = w * s;
    const int   ix0 = (int)cx;
    const float fx  = cx - ix0;

    const float2* gp = gnodes + ((((size_t)b * DIMN + d) * DIMN + h) * 3) * GSZ;
    const float2 p0 = __ldg(gp + ix0);
    const float2 p1 = __ldg(gp + GSZ + ix0);
    const float2 p2 = __ldg(gp + 2 * GSZ + ix0);
    const float upx = p0.x + fx * (p0.y - p0.x);
    const float upy = p1.x + fx * (p1.y - p1.x);
    const float upz = p2.x + fx * (p2.y - p2.x);

    // ---- warp coordinate: voxel + up*(n-1)/2, mirror-reflect (single fold) ----
    const float px = reflect1((float)w + upx * 79.5f);
    const float py = reflect1((float)h + upy * 79.5f);
    const float pz = reflect1((float)d + upz * 79.5f);

    // px,py,pz in [0,159] -> floor tap needs no clamp
    const int jx0 = (int)px;
    const int jy0 = (int)py;
    const int jz0 = (int)pz;
    const float ax = px - (float)jx0;
    const float ay = py - (float)jy0;
    const float az = pz - (float)jz0;

    const int dx = (jx0 < DIMN - 1) ? 1         : 0;
    const int dy = (jy0 < DIMN - 1) ? DIMN      : 0;
    const int dz = (jz0 < DIMN - 1) ? DIMN*DIMN : 0;

    const float bx0 = 1.0f - ax, by0 = 1.0f - ay, bz0 = 1.0f - az;
    const float w00 = bz0 * by0, w01 = bz0 * ay;
    const float w10 = az * by0,  w11 = az * ay;
    float tw[8];
    tw[0] = w00 * bx0;  tw[1] = w00 * ax;
    tw[2] = w01 * bx0;  tw[3] = w01 * ax;
    tw[4] = w10 * bx0;  tw[5] = w10 * ax;
    tw[6] = w11 * bx0;  tw[7] = w11 * ax;

    const int base = (jz0 * DIMN + jy0) * DIMN + jx0;
    int off[8];
    off[0] = base;          off[1] = base + dx;
    off[2] = off[0] + dy;   off[3] = off[2] + dx;
    off[4] = off[0] + dz;   off[5] = off[4] + dx;
    off[6] = off[4] + dy;   off[7] = off[6] + dx;

    const float* __restrict__ x0 = x + (size_t)b * 2 * N3;   // ch0; +N3 = ch1

    float t0[8], t1[8];
    #pragma unroll
    for (int k = 0; k < 8; k++) {
        const float* p = x0 + off[k];
        t0[k] = __ldg(p);
        t1[k] = __ldg(p + N3);
    }

    float v0 = 0.f, v1 = 0.f;
    #pragma unroll
    for (int k = 0; k < 8; k++) {
        v0 = fmaf(tw[k], t0[k], v0);
        v1 = fmaf(tw[k], t1[k], v1);
    }

    const int spatial = (d * DIMN + h) * DIMN + w;
    float* __restrict__ o0 = out + (size_t)b * 2 * N3;
    o0[spatial]      = v0;
    o0[N3 + spatial] = v1;
}

extern "C" void kernel_launch(void* const* d_in, const int* in_sizes, int n_in,
                              void* d_out, int out_size) {
    const float* x    = (const float*)d_in[0];
    const float* flow = (const float*)d_in[1];
    float* out        = (float*)d_out;

    dim3 pblock(192);                  // 32 h-lines x 3 comp x 2 halves
    dim3 pgrid(5, DIMN, 4);            // (h-tiles, d, b)
    flow_nodes_kernel<<<pgrid, pblock>>>(flow);

    dim3 block(32, 8);                 // 256 threads: 32 w x 8 h
    dim3 grid(5, 20 * DIMN, 4);        // (w-tiles, h-tiles*d, b)
    elastic_kernel<<<grid, block>>>(x, out);
}

// round 11
// speedup vs baseline: 1.0394x; 1.0004x over previous
#include <cuda_runtime.h>
#include <cuda_bf16.h>

#define GSZ 8
#define DIMN 160
#define N3 (DIMN*DIMN*DIMN)
#define NLINE (4 * DIMN * DIMN)               // b * d * h lines

// Precomputed per-(b,d,h) x-node lerp pairs, split planes:
//   gA[line*8+i] = (c0: g[i], g[i+1]) , (c1: g[i], g[i+1])   -> one LDG.128
//   gB[line*8+i] = (c2: g[i], g[i+1])                        -> one LDG.64
__device__ float4 gA[NLINE * GSZ];            // 13.1 MB
__device__ float2 gB[NLINE * GSZ];            // 6.55 MB

// One thread per (b, d, h, node): computes all 3 components' pairs for its node.
// block = 256 = 32 h-lines x 8 nodes ; grid = (5 h-tiles, 160 d, 4 b)
__global__ void __launch_bounds__(256) flow_nodes_kernel(
    const float* __restrict__ flow)           // [B,3,8,8,8]
{
    const int tid  = threadIdx.x;
    const int node = tid & 7;                 // 0..7
    const int hl   = tid >> 3;                // 0..31
    const int h    = blockIdx.x * 32 + hl;
    const int d    = blockIdx.y;
    const int b    = blockIdx.z;

    const float s = 7.0f / 159.0f;
    const float cz = d * s, cy = h * s;
    const int   iz0 = (int)cz, iy0 = (int)cy;
    const float fz = cz - iz0, fy = cy - iy0;
    const int   iz1 = min(iz0 + 1, GSZ - 1);
    const int   iy1 = min(iy0 + 1, GSZ - 1);

    const int r00 = (iz0 * GSZ + iy0) * GSZ;
    const int r01 = (iz0 * GSZ + iy1) * GSZ;
    const int r10 = (iz1 * GSZ + iy0) * GSZ;
    const int r11 = (iz1 * GSZ + iy1) * GSZ;
    const int n1  = min(node + 1, GSZ - 1);

    float gi[3], gn[3];
    #pragma unroll
    for (int c = 0; c < 3; c++) {
        const float* fb = flow + (((size_t)b * 3 + c) << 9);   // *512
        // node i
        {
            const float a0 = __ldg(fb + r00 + node);
            const float a1 = __ldg(fb + r01 + node);
            const float a2 = __ldg(fb + r10 + node);
            const float a3 = __ldg(fb + r11 + node);
            const float v0 = a0 + fy * (a1 - a0);
            const float v1 = a2 + fy * (a3 - a2);
            gi[c] = v0 + fz * (v1 - v0);
        }
        // node i+1 (clamped)
        {
            const float a0 = __ldg(fb + r00 + n1);
            const float a1 = __ldg(fb + r01 + n1);
            const float a2 = __ldg(fb + r10 + n1);
            const float a3 = __ldg(fb + r11 + n1);
            const float v0 = a0 + fy * (a1 - a0);
            const float v1 = a2 + fy * (a3 - a2);
            gn[c] = v0 + fz * (v1 - v0);
        }
    }

    const size_t line8 = (((size_t)b * DIMN + d) * DIMN + h) * GSZ + node;
    float4 qa; qa.x = gi[0]; qa.y = gn[0]; qa.z = gi[1]; qa.w = gn[1];
    float2 qb; qb.x = gi[2]; qb.y = gn[2];
    gA[line8] = qa;
    gB[line8] = qb;
}

__device__ __forceinline__ float reflect1(float c) {
    // mirror, period 2*(n-1)=318; single fold valid since |delta| <= ~16
    c = fabsf(c);
    return (c > 159.0f) ? (318.0f - c) : c;
}

__global__ void __launch_bounds__(256) elastic_kernel(
    const float* __restrict__ x,       // [B,2,160,160,160]
    float* __restrict__ out)           // [B,2,160,160,160]
{
    // block: 32 w x 8 h ; grid: (5 w-tiles, 20 h-tiles * 160 d, 4 b)
    const int b  = blockIdx.z;
    const int d  = blockIdx.y / 20;
    const int ht = blockIdx.y % 20;
    const int tx = threadIdx.x;
    const int h  = ht * 8 + threadIdx.y;
    const int w  = blockIdx.x * 32 + tx;

    // ---- coarse flow: LDG.128 + LDG.64 from packed node pairs ----
    const float s = 7.0f / 159.0f;
    const float cx  = w * s;
    const int   ix0 = (int)cx;
    const float fx  = cx - ix0;

    const size_t line8 = (((size_t)b * DIMN + d) * DIMN + h) * GSZ + ix0;
    const float4 qa = __ldg(gA + line8);
    const float2 qb = __ldg(gB + line8);
    const float upx = qa.x + fx * (qa.y - qa.x);
    const float upy = qa.z + fx * (qa.w - qa.z);
    const float upz = qb.x + fx * (qb.y - qb.x);

    // ---- warp coordinate: voxel + up*(n-1)/2, mirror-reflect (single fold) ----
    const float px = reflect1((float)w + upx * 79.5f);
    const float py = reflect1((float)h + upy * 79.5f);
    const float pz = reflect1((float)d + upz * 79.5f);

    // px,py,pz in [0,159] -> floor tap needs no clamp
    const int jx0 = (int)px;
    const int jy0 = (int)py;
    const int jz0 = (int)pz;
    const float ax = px - (float)jx0;
    const float ay = py - (float)jy0;
    const float az = pz - (float)jz0;

    const int dx = (jx0 < DIMN - 1) ? 1         : 0;
    const int dy = (jy0 < DIMN - 1) ? DIMN      : 0;
    const int dz = (jz0 < DIMN - 1) ? DIMN*DIMN : 0;

    const float bx0 = 1.0f - ax, by0 = 1.0f - ay, bz0 = 1.0f - az;
    const float w00 = bz0 * by0, w01 = bz0 * ay;
    const float w10 = az * by0,  w11 = az * ay;
    float tw[8];
    tw[0] = w00 * bx0;  tw[1] = w00 * ax;
    tw[2] = w01 * bx0;  tw[3] = w01 * ax;
    tw[4] = w10 * bx0;  tw[5] = w10 * ax;
    tw[6] = w11 * bx0;  tw[7] = w11 * ax;

    const int base = (jz0 * DIMN + jy0) * DIMN + jx0;
    int off[8];
    off[0] = base;          off[1] = base + dx;
    off[2] = off[0] + dy;   off[3] = off[2] + dx;
    off[4] = off[0] + dz;   off[5] = off[4] + dx;
    off[6] = off[4] + dy;   off[7] = off[6] + dx;

    const float* __restrict__ x0 = x + (size_t)b * 2 * N3;   // ch0; +N3 = ch1

    float t0[8], t1[8];
    #pragma unroll
    for (int k = 0; k < 8; k++) {
        const float* p = x0 + off[k];
        t0[k] = __ldg(p);
        t1[k] = __ldg(p + N3);
    }

    float v0 = 0.f, v1 = 0.f;
    #pragma unroll
    for (int k = 0; k < 8; k++) {
        v0 = fmaf(tw[k], t0[k], v0);
        v1 = fmaf(tw[k], t1[k], v1);
    }

    const int spatial = (d * DIMN + h) * DIMN + w;
    float* __restrict__ o0 = out + (size_t)b * 2 * N3;
    o0[spatial]      = v0;
    o0[N3 + spatial] = v1;
}

extern "C" void kernel_launch(void* const* d_in, const int* in_sizes, int n_in,
                              void* d_out, int out_size) {
    const float* x    = (const float*)d_in[0];
    const float* flow = (const float*)d_in[1];
    float* out        = (float*)d_out;

    dim3 pblock(256);                  // 32 h-lines x 8 nodes
    dim3 pgrid(5, DIMN, 4);            // (h-tiles, d, b)
    flow_nodes_kernel<<<pgrid, pblock>>>(flow);

    dim3 block(32, 8);                 // 256 threads: 32 w x 8 h
    dim3 grid(5, 20 * DIMN, 4);        // (w-tiles, h-tiles*d, b)
    elastic_kernel<<<grid, block>>>(x, out);
}

// round 12
// speedup vs baseline: 1.0537x; 1.0138x over previous
#include <cuda_runtime.h>
#include <cuda_bf16.h>

#define GSZ 8
#define DIMN 160
#define N3 (DIMN*DIMN*DIMN)
#define NLINE (4 * DIMN * DIMN)               // b * d * h lines

// Precomputed per-(b,d,h) x-node lerp pairs, split planes:
//   gA[line*8+i] = (c0: g[i], g[i+1]) , (c1: g[i], g[i+1])   -> one LDG.128
//   gB[line*8+i] = (c2: g[i], g[i+1])                        -> one LDG.64
__device__ float4 gA[NLINE * GSZ];            // 13.1 MB
__device__ float2 gB[NLINE * GSZ];            // 6.55 MB

// One thread per (b, d, h, node): computes ONLY its node's 3 component values;
// the pair partner g[node+1] arrives via shfl from lane+1 (node 7 clamps to self).
// block = 256 = 32 h-lines x 8 nodes ; grid = (5 h-tiles, 160 d, 4 b)
__global__ void __launch_bounds__(256) flow_nodes_kernel(
    const float* __restrict__ flow)           // [B,3,8,8,8]
{
    const int tid  = threadIdx.x;
    const int node = tid & 7;                 // 0..7 ; lane+1 == node+1 within group
    const int hl   = tid >> 3;                // 0..31
    const int h    = blockIdx.x * 32 + hl;
    const int d    = blockIdx.y;
    const int b    = blockIdx.z;

    const float s = 7.0f / 159.0f;
    const float cz = d * s, cy = h * s;
    const int   iz0 = (int)cz, iy0 = (int)cy;
    const float fz = cz - iz0, fy = cy - iy0;
    const int   iz1 = min(iz0 + 1, GSZ - 1);
    const int   iy1 = min(iy0 + 1, GSZ - 1);

    const int r00 = (iz0 * GSZ + iy0) * GSZ + node;
    const int r01 = (iz0 * GSZ + iy1) * GSZ + node;
    const int r10 = (iz1 * GSZ + iy0) * GSZ + node;
    const int r11 = (iz1 * GSZ + iy1) * GSZ + node;

    float gi[3];
    #pragma unroll
    for (int c = 0; c < 3; c++) {
        const float* fb = flow + (((size_t)b * 3 + c) << 9);   // *512
        const float a0 = __ldg(fb + r00);
        const float a1 = __ldg(fb + r01);
        const float a2 = __ldg(fb + r10);
        const float a3 = __ldg(fb + r11);
        const float v0 = a0 + fy * (a1 - a0);
        const float v1 = a2 + fy * (a3 - a2);
        gi[c] = v0 + fz * (v1 - v0);
    }

    // pair partner from neighbor lane; node 7 -> clamp to own value
    float gn[3];
    #pragma unroll
    for (int c = 0; c < 3; c++) {
        const float nb = __shfl_down_sync(0xffffffffu, gi[c], 1);
        gn[c] = (node == 7) ? gi[c] : nb;
    }

    const size_t line8 = (((size_t)b * DIMN + d) * DIMN + h) * GSZ + node;
    float4 qa; qa.x = gi[0]; qa.y = gn[0]; qa.z = gi[1]; qa.w = gn[1];
    float2 qb; qb.x = gi[2]; qb.y = gn[2];
    gA[line8] = qa;
    gB[line8] = qb;
}

__device__ __forceinline__ float reflect1(float c) {
    // mirror, period 2*(n-1)=318; single fold valid since |delta| <= ~16
    c = fabsf(c);
    return (c > 159.0f) ? (318.0f - c) : c;
}

__global__ void __launch_bounds__(256) elastic_kernel(
    const float* __restrict__ x,       // [B,2,160,160,160]
    float* __restrict__ out)           // [B,2,160,160,160]
{
    // block: 32 w x 8 h ; grid: (5 w-tiles, 20 h-tiles * 160 d, 4 b)
    const int b  = blockIdx.z;
    const int d  = blockIdx.y / 20;
    const int ht = blockIdx.y % 20;
    const int tx = threadIdx.x;
    const int h  = ht * 8 + threadIdx.y;
    const int w  = blockIdx.x * 32 + tx;

    // ---- coarse flow: LDG.128 + LDG.64 from packed node pairs ----
    const float s = 7.0f / 159.0f;
    const float cx  = w * s;
    const int   ix0 = (int)cx;
    const float fx  = cx - ix0;

    const size_t line8 = (((size_t)b * DIMN + d) * DIMN + h) * GSZ + ix0;
    const float4 qa = __ldg(gA + line8);
    const float2 qb = __ldg(gB + line8);
    const float upx = qa.x + fx * (qa.y - qa.x);
    const float upy = qa.z + fx * (qa.w - qa.z);
    const float upz = qb.x + fx * (qb.y - qb.x);

    // ---- warp coordinate: voxel + up*(n-1)/2, mirror-reflect (single fold) ----
    const float px = reflect1((float)w + upx * 79.5f);
    const float py = reflect1((float)h + upy * 79.5f);
    const float pz = reflect1((float)d + upz * 79.5f);

    // px,py,pz in [0,159] -> floor tap needs no clamp
    const int jx0 = (int)px;
    const int jy0 = (int)py;
    const int jz0 = (int)pz;
    const float ax = px - (float)jx0;
    const float ay = py - (float)jy0;
    const float az = pz - (float)jz0;

    const int dx = (jx0 < DIMN - 1) ? 1         : 0;
    const int dy = (jy0 < DIMN - 1) ? DIMN      : 0;
    const int dz = (jz0 < DIMN - 1) ? DIMN*DIMN : 0;

    const float bx0 = 1.0f - ax, by0 = 1.0f - ay, bz0 = 1.0f - az;
    const float w00 = bz0 * by0, w01 = bz0 * ay;
    const float w10 = az * by0,  w11 = az * ay;
    float tw[8];
    tw[0] = w00 * bx0;  tw[1] = w00 * ax;
    tw[2] = w01 * bx0;  tw[3] = w01 * ax;
    tw[4] = w10 * bx0;  tw[5] = w10 * ax;
    tw[6] = w11 * bx0;  tw[7] = w11 * ax;

    const int base = (jz0 * DIMN + jy0) * DIMN + jx0;
    int off[8];
    off[0] = base;          off[1] = base + dx;
    off[2] = off[0] + dy;   off[3] = off[2] + dx;
    off[4] = off[0] + dz;   off[5] = off[4] + dx;
    off[6] = off[4] + dy;   off[7] = off[6] + dx;

    const float* __restrict__ x0 = x + (size_t)b * 2 * N3;   // ch0; +N3 = ch1

    float t0[8], t1[8];
    #pragma unroll
    for (int k = 0; k < 8; k++) {
        const float* p = x0 + off[k];
        t0[k] = __ldg(p);
        t1[k] = __ldg(p + N3);
    }

    float v0 = 0.f, v1 = 0.f;
    #pragma unroll
    for (int k = 0; k < 8; k++) {
        v0 = fmaf(tw[k], t0[k], v0);
        v1 = fmaf(tw[k], t1[k], v1);
    }

    const int spatial = (d * DIMN + h) * DIMN + w;
    float* __restrict__ o0 = out + (size_t)b * 2 * N3;
    o0[spatial]      = v0;
    o0[N3 + spatial] = v1;
}

extern "C" void kernel_launch(void* const* d_in, const int* in_sizes, int n_in,
                              void* d_out, int out_size) {
    const float* x    = (const float*)d_in[0];
    const float* flow = (const float*)d_in[1];
    float* out        = (float*)d_out;

    dim3 pblock(256);                  // 32 h-lines x 8 nodes
    dim3 pgrid(5, DIMN, 4);            // (h-tiles, d, b)
    flow_nodes_kernel<<<pgrid, pblock>>>(flow);

    dim3 block(32, 8);                 // 256 threads: 32 w x 8 h
    dim3 grid(5, 20 * DIMN, 4);        // (w-tiles, h-tiles*d, b)
    elastic_kernel<<<grid, block>>>(x, out);
}

// round 13
// speedup vs baseline: 1.0558x; 1.0020x over previous
#include <cuda_runtime.h>
#include <cuda_bf16.h>

#define GSZ 8
#define DIMN 160
#define N3 (DIMN*DIMN*DIMN)
#define NLINE (4 * DIMN * DIMN)               // b * d * h lines

// Precomputed per-(b,d,h) x-node lerp pairs, split planes:
//   gA[line*8+i] = (c0: g[i], g[i+1]) , (c1: g[i], g[i+1])   -> one LDG.128
//   gB[line*8+i] = (c2: g[i], g[i+1])                        -> one LDG.64
__device__ float4 gA[NLINE * GSZ];            // 13.1 MB
__device__ float2 gB[NLINE * GSZ];            // 6.55 MB

// One thread per (b, d, h, node): computes ONLY its node's 3 component values;
// the pair partner g[node+1] arrives via shfl from lane+1 (node 7 clamps to self).
// block = 256 = 32 h-lines x 8 nodes ; grid = (5 h-tiles, 160 d, 4 b)
__global__ void __launch_bounds__(256) flow_nodes_kernel(
    const float* __restrict__ flow)           // [B,3,8,8,8]
{
    const int tid  = threadIdx.x;
    const int node = tid & 7;
    const int hl   = tid >> 3;
    const int h    = blockIdx.x * 32 + hl;
    const int d    = blockIdx.y;
    const int b    = blockIdx.z;

    const float s = 7.0f / 159.0f;
    const float cz = d * s, cy = h * s;
    const int   iz0 = (int)cz, iy0 = (int)cy;
    const float fz = cz - iz0, fy = cy - iy0;
    const int   iz1 = min(iz0 + 1, GSZ - 1);
    const int   iy1 = min(iy0 + 1, GSZ - 1);

    const int r00 = (iz0 * GSZ + iy0) * GSZ + node;
    const int r01 = (iz0 * GSZ + iy1) * GSZ + node;
    const int r10 = (iz1 * GSZ + iy0) * GSZ + node;
    const int r11 = (iz1 * GSZ + iy1) * GSZ + node;

    float gi[3];
    #pragma unroll
    for (int c = 0; c < 3; c++) {
        const float* fb = flow + (((size_t)b * 3 + c) << 9);   // *512
        const float a0 = __ldg(fb + r00);
        const float a1 = __ldg(fb + r01);
        const float a2 = __ldg(fb + r10);
        const float a3 = __ldg(fb + r11);
        const float v0 = a0 + fy * (a1 - a0);
        const float v1 = a2 + fy * (a3 - a2);
        gi[c] = v0 + fz * (v1 - v0);
    }

    float gn[3];
    #pragma unroll
    for (int c = 0; c < 3; c++) {
        const float nb = __shfl_down_sync(0xffffffffu, gi[c], 1);
        gn[c] = (node == 7) ? gi[c] : nb;
    }

    const size_t line8 = (((size_t)b * DIMN + d) * DIMN + h) * GSZ + node;
    float4 qa; qa.x = gi[0]; qa.y = gn[0]; qa.z = gi[1]; qa.w = gn[1];
    float2 qb; qb.x = gi[2]; qb.y = gn[2];
    gA[line8] = qa;
    gB[line8] = qb;
}

__device__ __forceinline__ float reflect1(float c) {
    // mirror, period 2*(n-1)=318; single fold valid since |delta| <= ~16
    c = fabsf(c);
    return (c > 159.0f) ? (318.0f - c) : c;
}

// Compute the 8 tap offsets + fracs for one voxel.
__device__ __forceinline__ void voxel_setup(
    int b, int d, int h, int w, int ix0, float fx,
    int* off, float& ax, float& ay, float& az)
{
    const size_t line8 = (((size_t)b * DIMN + d) * DIMN + h) * GSZ + ix0;
    const float4 qa = __ldg(gA + line8);
    const float2 qb = __ldg(gB + line8);
    const float upx = qa.x + fx * (qa.y - qa.x);
    const float upy = qa.z + fx * (qa.w - qa.z);
    const float upz = qb.x + fx * (qb.y - qb.x);

    const float px = reflect1((float)w + upx * 79.5f);
    const float py = reflect1((float)h + upy * 79.5f);
    const float pz = reflect1((float)d + upz * 79.5f);

    const int jx0 = (int)px;
    const int jy0 = (int)py;
    const int jz0 = (int)pz;
    ax = px - (float)jx0;
    ay = py - (float)jy0;
    az = pz - (float)jz0;

    const int dx = (jx0 < DIMN - 1) ? 1         : 0;
    const int dy = (jy0 < DIMN - 1) ? DIMN      : 0;
    const int dz = (jz0 < DIMN - 1) ? DIMN*DIMN : 0;

    const int base = (jz0 * DIMN + jy0) * DIMN + jx0;
    off[0] = base;          off[1] = base + dx;
    off[2] = off[0] + dy;   off[3] = off[2] + dx;
    off[4] = off[0] + dz;   off[5] = off[4] + dx;
    off[6] = off[4] + dy;   off[7] = off[6] + dx;
}

__device__ __forceinline__ void make_weights(float ax, float ay, float az, float* tw)
{
    const float bx0 = 1.0f - ax, by0 = 1.0f - ay, bz0 = 1.0f - az;
    const float w00 = bz0 * by0, w01 = bz0 * ay;
    const float w10 = az * by0,  w11 = az * ay;
    tw[0] = w00 * bx0;  tw[1] = w00 * ax;
    tw[2] = w01 * bx0;  tw[3] = w01 * ax;
    tw[4] = w10 * bx0;  tw[5] = w10 * ax;
    tw[6] = w11 * bx0;  tw[7] = w11 * ax;
}

__global__ void __launch_bounds__(256) elastic_kernel(
    const float* __restrict__ x,       // [B,2,160,160,160]
    float* __restrict__ out)           // [B,2,160,160,160]
{
    // block: 32 w x 8 ty, each thread does voxels (w, h) and (w, h+8).
    // grid: (5 w-tiles, 10 h-tiles * 160 d, 4 b)
    const int b  = blockIdx.z;
    const int d  = blockIdx.y / 10;
    const int ht = blockIdx.y % 10;
    const int tx = threadIdx.x;
    const int hA = ht * 16 + threadIdx.y;
    const int hB = hA + 8;
    const int w  = blockIdx.x * 32 + tx;

    // shared across both voxels (same w)
    const float s = 7.0f / 159.0f;
    const float cx  = w * s;
    const int   ix0 = (int)cx;
    const float fx  = cx - ix0;

    int offA[8], offB[8];
    float axA, ayA, azA, axB, ayB, azB;
    voxel_setup(b, d, hA, w, ix0, fx, offA, axA, ayA, azA);
    voxel_setup(b, d, hB, w, ix0, fx, offB, axB, ayB, azB);

    const float* __restrict__ x0 = x + (size_t)b * 2 * N3;   // ch0; +N3 = ch1

    // front-batch all 32 gather loads (2 voxels x 2 channels x 8 taps)
    float tA0[8], tA1[8], tB0[8], tB1[8];
    #pragma unroll
    for (int k = 0; k < 8; k++) {
        const float* p = x0 + offA[k];
        tA0[k] = __ldg(p);
        tA1[k] = __ldg(p + N3);
    }
    #pragma unroll
    for (int k = 0; k < 8; k++) {
        const float* p = x0 + offB[k];
        tB0[k] = __ldg(p);
        tB1[k] = __ldg(p + N3);
    }

    // weights computed while loads are in flight
    float twA[8], twB[8];
    make_weights(axA, ayA, azA, twA);
    make_weights(axB, ayB, azB, twB);

    float vA0 = 0.f, vA1 = 0.f, vB0 = 0.f, vB1 = 0.f;
    #pragma unroll
    for (int k = 0; k < 8; k++) {
        vA0 = fmaf(twA[k], tA0[k], vA0);
        vA1 = fmaf(twA[k], tA1[k], vA1);
        vB0 = fmaf(twB[k], tB0[k], vB0);
        vB1 = fmaf(twB[k], tB1[k], vB1);
    }

    const int spatialA = (d * DIMN + hA) * DIMN + w;
    const int spatialB = spatialA + 8 * DIMN;
    float* __restrict__ o0 = out + (size_t)b * 2 * N3;
    o0[spatialA]      = vA0;
    o0[N3 + spatialA] = vA1;
    o0[spatialB]      = vB0;
    o0[N3 + spatialB] = vB1;
}

extern "C" void kernel_launch(void* const* d_in, const int* in_sizes, int n_in,
                              void* d_out, int out_size) {
    const float* x    = (const float*)d_in[0];
    const float* flow = (const float*)d_in[1];
    float* out        = (float*)d_out;

    dim3 pblock(256);                  // 32 h-lines x 8 nodes
    dim3 pgrid(5, DIMN, 4);            // (h-tiles, d, b)
    flow_nodes_kernel<<<pgrid, pblock>>>(flow);

    dim3 block(32, 8);                 // 256 threads, 2 voxels each
    dim3 grid(5, 10 * DIMN, 4);        // (w-tiles, h-tiles*d, b)
    elastic_kernel<<<grid, block>>>(x, out);
}